// round 14
// baseline (speedup 1.0000x reference)
#include <cuda_runtime.h>
#include <cuda_fp16.h>

// feature_map [512,512,64] f32, boxes [512,4] f32 (cx,cy,w,h), out [512,32,32,64] f32
#define IN_H    512
#define IN_W    512
#define NC8     8           // channels as 8-channel groups (uint4 of 4 half2)
#define NBOX    512
#define OUTW    32
#define OYT     8           // oy rows per CTA tile (min row overlap)
#define NTILES  (OUTW / OYT)
#define MAXTAPS 36          // ks < 16 -> taps <= 34; +pair pad
#define MAXROWS 152         // union of 8 oy windows: 7*inv + 2ks + 2 < 146

typedef unsigned long long ull;

// fp16 staged copy of the feature map (32 MB device scratch; legal per rules).
// +64 px pad: pair-tap loop may read 1 px past the logical end at
// (row 511, rightmost window) with zero weight; pad is zero-init .bss.
__device__ uint4 g_fm16[(IN_H * IN_W + 64) * NC8];

// ---- pre-pass: f32 -> fp16 conversion, fully coalesced ----
__global__ __launch_bounds__(1024)
void convert_kernel(const float* __restrict__ fm)
{
    int i = blockIdx.x * 1024 + threadIdx.x;   // one c8 group per thread
    const float4 v0 = ((const float4*)fm)[2 * i];
    const float4 v1 = ((const float4*)fm)[2 * i + 1];
    __half2 a = __floats2half2_rn(v0.x, v0.y);
    __half2 b = __floats2half2_rn(v0.z, v0.w);
    __half2 c = __floats2half2_rn(v1.x, v1.y);
    __half2 d = __floats2half2_rn(v1.z, v1.w);
    uint4 o;
    o.x = *reinterpret_cast<unsigned*>(&a);
    o.y = *reinterpret_cast<unsigned*>(&b);
    o.z = *reinterpret_cast<unsigned*>(&c);
    o.w = *reinterpret_cast<unsigned*>(&d);
    g_fm16[i] = o;
}

// half2 (packed in u32) -> f32x2 (packed in u64), lane order preserved
__device__ __forceinline__ ull h2f(unsigned h2)
{
    ull r;
    asm("{\n\t"
        ".reg .f16 a, b;\n\t"
        ".reg .f32 lo, hi;\n\t"
        "mov.b32 {a, b}, %1;\n\t"
        "cvt.f32.f16 lo, a;\n\t"
        "cvt.f32.f16 hi, b;\n\t"
        "mov.b64 %0, {lo, hi};\n\t"
        "}" : "=l"(r) : "r"(h2));
    return r;
}

// packed dual-FMA: acc.lane += v.lane * w.lane  (IEEE f32 per lane)
#define FMA2(acc, v, w) \
    asm("fma.rn.f32x2 %0, %1, %2, %0;" : "+l"(acc) : "l"(v), "l"(w))

// One CTA per (oy-tile of 8, box, channel-half). 128 threads = 32 ox x 4 c8.
// The c-split lets OYT=8 (minimal row re-reads, x-conv done once per union
// row per channel) fit in 32 accumulator regs. The two c-half CTAs read
// disjoint 16B halves of each pixel -> no byte duplication.
// Inner loop identical to the verified R12 kernel (fp16 loads, f32x2 math).
// Weight math replicates jax.image.scale_and_translate(method="linear",
// antialias=True) exactly (formulas verified since R4).
__global__ __launch_bounds__(128, 8)
void roi_align_kernel(const float* __restrict__ boxes,
                      float* __restrict__ out)
{
    __shared__ float2 s_wx2[OUTW * MAXTAPS];    // x weights, duplicated {w,w}
    __shared__ int    s_xb[OUTW];               // x window base per ox
    __shared__ float  s_sy[OYT];                // y sample pos per tile oy
    __shared__ float  s_invn[OYT];              // y norm (0 if invalid)
    __shared__ int    s_yb[OYT];                // y window base per tile oy
    __shared__ float2 s_wyt2[MAXROWS * OYT];    // y weights, duplicated {w,w}

    const int tile  = blockIdx.x;   // 0..3
    const int box   = blockIdx.y;   // 0..511
    const int chalf = blockIdx.z;   // 0..1
    const int tid   = threadIdx.x;

    // ---- box parameters (all threads) ----
    const float4 b = ((const float4*)boxes)[box];
    float x0 = b.x - b.z * 0.5f;           // pre-clamp w/h (reference order)
    float y0 = b.y - b.w * 0.5f;
    float bw = fmaxf(b.z, 1e-6f);
    float bh = fmaxf(b.w, 1e-6f);

    float scale_x = 32.0f / (bw * 512.0f);
    float inv_x   = 1.0f / scale_x;
    float ks_x    = fmaxf(inv_x, 1.0f);
    float toff_x  = ((-x0 * 32.0f) / bw) * inv_x;
    int   ntx     = min((int)(2.0f * ks_x) + 2, 34);

    float scale_y = 32.0f / (bh * 512.0f);
    float inv_y   = 1.0f / scale_y;
    float ks_y    = fmaxf(inv_y, 1.0f);
    float toff_y  = ((-y0 * 32.0f) / bh) * inv_y;
    int   nty     = min((int)(2.0f * ks_y) + 2, 34);
    float rks_y   = 1.0f / ks_y;

    // ---- phase 1: per-ox x weights (threads 0..31), per-oy y params (32..39)
    if (tid < OUTW) {
        const int ox = tid;
        float s    = ((float)ox + 0.5f) * inv_x - toff_x - 0.5f;
        int   base = min(max((int)ceilf(s - ks_x), 0), IN_W - ntx);
        float rks  = 1.0f / ks_x;
        float norm = 0.0f;
        for (int j = 0; j < ntx; j++)
            norm += fmaxf(0.0f, 1.0f - fabsf(s - (float)(base + j)) * rks);
        bool valid = (s >= -0.5f) && (s <= (float)IN_W - 0.5f)
                     && (fabsf(norm) > 1.1920929e-4f);   // 1000 * eps_f32
        float invn = valid ? (1.0f / norm) : 0.0f;
        for (int j = 0; j < ntx; j++) {
            float w = fmaxf(0.0f, 1.0f - fabsf(s - (float)(base + j)) * rks) * invn;
            s_wx2[ox * MAXTAPS + j] = make_float2(w, w);
        }
        // zero-pad one tap (pair loop rounds ntx up to even; ntx+1 <= 35 < 36)
        s_wx2[ox * MAXTAPS + ntx] = make_float2(0.f, 0.f);
        s_xb[ox] = base;
    } else if (tid < OUTW + OYT) {
        const int k  = tid - OUTW;
        const int oy = tile * OYT + k;
        float sy = ((float)oy + 0.5f) * inv_y - toff_y - 0.5f;
        int   yb = min(max((int)ceilf(sy - ks_y), 0), IN_H - nty);
        float norm = 0.0f;
        for (int j = 0; j < nty; j++)
            norm += fmaxf(0.0f, 1.0f - fabsf(sy - (float)(yb + j)) * rks_y);
        bool valid = (sy >= -0.5f) && (sy <= (float)IN_H - 0.5f)
                     && (fabsf(norm) > 1.1920929e-4f);
        s_sy[k]   = sy;
        s_invn[k] = valid ? (1.0f / norm) : 0.0f;
        s_yb[k]   = yb;
    }
    __syncthreads();

    // ---- phase 2: fill duplicated wy table over the row union ----
    const int rmin   = s_yb[0];                       // sy monotone in k
    const int rcount = s_yb[OYT - 1] + nty - rmin;    // <= 146
    for (int idx = tid; idx < rcount * OYT; idx += 128) {
        int r = idx >> 3, k = idx & (OYT - 1);
        float w = fmaxf(0.0f, 1.0f - fabsf(s_sy[k] - (float)(rmin + r)) * rks_y)
                  * s_invn[k];
        s_wyt2[idx] = make_float2(w, w);
    }
    __syncthreads();

    // active rows form one interval (y-windows of the 8 oy overlap)
    const int rlo = max(rmin, (int)ceilf(s_sy[0] - ks_y));
    const int rhi = min(rmin + rcount, (int)floorf(s_sy[OYT - 1] + ks_y) + 1);

    // ---- main loop: thread = (ox, c8 of this half); 8 oy x 8 ch accums ----
    const int ox = tid >> 2;                 // 0..31
    const int c8 = chalf * 4 + (tid & 3);    // 0..7
    const ulonglong2* __restrict__ wxp =
        (const ulonglong2*)&s_wx2[ox * MAXTAPS];   // 16B-aligned weight pairs
    const int np = (ntx + 1) >> 1;                 // tap pairs (zero-padded)

    // acc[k][p]: oy k (0..7), channel pair p (ch 2p, 2p+1)
    ull acc[OYT][4];
    #pragma unroll
    for (int k = 0; k < OYT; k++)
        #pragma unroll
        for (int p = 0; p < 4; p++) acc[k][p] = 0ull;

    const uint4* __restrict__ rowp =
        g_fm16 + ((size_t)rlo * IN_W + s_xb[ox]) * NC8 + c8;
    const ulonglong2* __restrict__ wyp =
        (const ulonglong2*)&s_wyt2[(rlo - rmin) * OYT];

    for (int r = rlo; r < rhi; r++) {
        // x convolution: pairs of taps, both LDG.128 issued before the FMAs
        ull r01 = 0, r23 = 0, r45 = 0, r67 = 0;
        const uint4* __restrict__ p = rowp;
        for (int jp = 0; jp < np; jp++) {
            uint4 v0 = p[0];
            uint4 v1 = p[NC8];                 // may touch zero-weight pad tap
            ulonglong2 w01 = wxp[jp];          // LDS.128: 2 duplicated weights
            FMA2(r01, h2f(v0.x), w01.x);
            FMA2(r23, h2f(v0.y), w01.x);
            FMA2(r45, h2f(v0.z), w01.x);
            FMA2(r67, h2f(v0.w), w01.x);
            FMA2(r01, h2f(v1.x), w01.y);
            FMA2(r23, h2f(v1.y), w01.y);
            FMA2(r45, h2f(v1.z), w01.y);
            FMA2(r67, h2f(v1.w), w01.y);
            p += 2 * NC8;
        }

        // scatter into 8 oy accumulators; wy pairs via 4 x LDS.128
        #pragma unroll
        for (int kp = 0; kp < 4; kp++) {
            ulonglong2 wy = wyp[kp];
            FMA2(acc[2*kp][0],   r01, wy.x);
            FMA2(acc[2*kp][1],   r23, wy.x);
            FMA2(acc[2*kp][2],   r45, wy.x);
            FMA2(acc[2*kp][3],   r67, wy.x);
            FMA2(acc[2*kp+1][0], r01, wy.y);
            FMA2(acc[2*kp+1][1], r23, wy.y);
            FMA2(acc[2*kp+1][2], r45, wy.y);
            FMA2(acc[2*kp+1][3], r67, wy.y);
        }

        rowp += IN_W * NC8;
        wyp  += 4;              // OYT pairs per row = 4 ulonglong2
    }

    // ---- write out[box][tile*8+k][ox][c8*8 .. +7] ----
    {
        float2* __restrict__ out2 = (float2*)out;
        size_t base =
            ((((size_t)box * OUTW + tile * OYT) * OUTW + ox) * NC8 + c8) * 4;
        const size_t st = (size_t)OUTW * NC8 * 4;   // one oy step in float2
        #pragma unroll
        for (int k = 0; k < OYT; k++) {
            out2[base + k * st + 0] = *reinterpret_cast<float2*>(&acc[k][0]);
            out2[base + k * st + 1] = *reinterpret_cast<float2*>(&acc[k][1]);
            out2[base + k * st + 2] = *reinterpret_cast<float2*>(&acc[k][2]);
            out2[base + k * st + 3] = *reinterpret_cast<float2*>(&acc[k][3]);
        }
    }
}

extern "C" void kernel_launch(void* const* d_in, const int* in_sizes, int n_in,
                              void* d_out, int out_size)
{
    const float* fm    = (const float*)d_in[0];   // [512, 512, 64] f32
    const float* boxes = (const float*)d_in[1];   // [512, 4] f32
    float* out = (float*)d_out;                   // [512, 32, 32, 64] f32

    // pre-pass: stage feature map as fp16 (2.1M c8-groups, 8 ch per thread)
    convert_kernel<<<(IN_H * IN_W * NC8) / 1024, 1024>>>(fm);

    dim3 grid(NTILES, NBOX, 2);   // (oy-tile, box, c-half) -> 4096 CTAs
    roi_align_kernel<<<grid, 128>>>(boxes, out);
}

// round 15
// speedup vs baseline: 1.3854x; 1.3854x over previous
#include <cuda_runtime.h>
#include <cuda_fp16.h>

// feature_map [512,512,64] f32, boxes [512,4] f32 (cx,cy,w,h), out [512,32,32,64] f32
#define IN_H    512
#define IN_W    512
#define NC8     8           // channels as 8-channel groups (uint4 of 4 half2)
#define NBOX    512
#define OUTW    32
#define OYT     4           // oy rows per CTA tile
#define NTILES  (OUTW / OYT)
#define MAXTAPS 36          // ks < 16 -> taps <= 34; +pair pad
#define MAXROWS 88          // union of 4 oy windows: 3*inv + 2ks + 2 <= 82

typedef unsigned long long ull;

// fp16 staged copy of the feature map (32 MB device scratch; legal per rules).
// +64 px pad: pair-tap loop may read 1 px past the logical end at
// (row 511, rightmost window) with zero weight; pad is zero-init .bss.
__device__ uint4 g_fm16[(IN_H * IN_W + 64) * NC8];

// ---- pre-pass: f32 -> fp16 conversion, fully coalesced ----
__global__ __launch_bounds__(1024)
void convert_kernel(const float* __restrict__ fm)
{
    int i = blockIdx.x * 1024 + threadIdx.x;   // one c8 group per thread
    const float4 v0 = ((const float4*)fm)[2 * i];
    const float4 v1 = ((const float4*)fm)[2 * i + 1];
    __half2 a = __floats2half2_rn(v0.x, v0.y);
    __half2 b = __floats2half2_rn(v0.z, v0.w);
    __half2 c = __floats2half2_rn(v1.x, v1.y);
    __half2 d = __floats2half2_rn(v1.z, v1.w);
    uint4 o;
    o.x = *reinterpret_cast<unsigned*>(&a);
    o.y = *reinterpret_cast<unsigned*>(&b);
    o.z = *reinterpret_cast<unsigned*>(&c);
    o.w = *reinterpret_cast<unsigned*>(&d);
    g_fm16[i] = o;
}

// half2 (packed in u32) -> f32x2 (packed in u64), lane order preserved
__device__ __forceinline__ ull h2f(unsigned h2)
{
    ull r;
    asm("{\n\t"
        ".reg .f16 a, b;\n\t"
        ".reg .f32 lo, hi;\n\t"
        "mov.b32 {a, b}, %1;\n\t"
        "cvt.f32.f16 lo, a;\n\t"
        "cvt.f32.f16 hi, b;\n\t"
        "mov.b64 %0, {lo, hi};\n\t"
        "}" : "=l"(r) : "r"(h2));
    return r;
}

// packed dual-FMA: acc.lane += v.lane * w.lane  (IEEE f32 per lane)
#define FMA2(acc, v, w) \
    asm("fma.rn.f32x2 %0, %1, %2, %0;" : "+l"(acc) : "l"(v), "l"(w))

// One CTA per (box, oy-tile of 4). 256 threads = 32 ox x 8 c8 lanes.
// R12 champion shape, plus an explicit software pipeline in the tap loop:
// the next pair's two LDG.128 are issued before the current pair's
// convert+FMA chain, guaranteeing >=4 loads in flight per warp.
// 3 CTAs/SM (85-reg budget) gives ptxas room for the prefetch registers.
// Weight math replicates jax.image.scale_and_translate(method="linear",
// antialias=True) exactly (formulas verified since R4).
__global__ __launch_bounds__(256, 3)
void roi_align_kernel(const float* __restrict__ boxes,
                      float* __restrict__ out)
{
    __shared__ float2 s_wx2[OUTW * MAXTAPS];    // x weights, duplicated {w,w}
    __shared__ int    s_xb[OUTW];               // x window base per ox
    __shared__ float  s_sy[OYT];                // y sample pos per tile oy
    __shared__ float  s_invn[OYT];              // y norm (0 if invalid)
    __shared__ int    s_yb[OYT];                // y window base per tile oy
    __shared__ float2 s_wyt2[MAXROWS * OYT];    // y weights, duplicated {w,w}

    const int tile = blockIdx.x;   // 0..7
    const int box  = blockIdx.y;   // 0..511
    const int tid  = threadIdx.x;

    // ---- box parameters (all threads) ----
    const float4 b = ((const float4*)boxes)[box];
    float x0 = b.x - b.z * 0.5f;           // pre-clamp w/h (reference order)
    float y0 = b.y - b.w * 0.5f;
    float bw = fmaxf(b.z, 1e-6f);
    float bh = fmaxf(b.w, 1e-6f);

    float scale_x = 32.0f / (bw * 512.0f);
    float inv_x   = 1.0f / scale_x;
    float ks_x    = fmaxf(inv_x, 1.0f);
    float toff_x  = ((-x0 * 32.0f) / bw) * inv_x;
    int   ntx     = min((int)(2.0f * ks_x) + 2, 34);

    float scale_y = 32.0f / (bh * 512.0f);
    float inv_y   = 1.0f / scale_y;
    float ks_y    = fmaxf(inv_y, 1.0f);
    float toff_y  = ((-y0 * 32.0f) / bh) * inv_y;
    int   nty     = min((int)(2.0f * ks_y) + 2, 34);
    float rks_y   = 1.0f / ks_y;

    // ---- phase 1: per-ox x weights (threads 0..31), per-oy y params (32..35)
    if (tid < OUTW) {
        const int ox = tid;
        float s    = ((float)ox + 0.5f) * inv_x - toff_x - 0.5f;
        int   base = min(max((int)ceilf(s - ks_x), 0), IN_W - ntx);
        float rks  = 1.0f / ks_x;
        float norm = 0.0f;
        for (int j = 0; j < ntx; j++)
            norm += fmaxf(0.0f, 1.0f - fabsf(s - (float)(base + j)) * rks);
        bool valid = (s >= -0.5f) && (s <= (float)IN_W - 0.5f)
                     && (fabsf(norm) > 1.1920929e-4f);   // 1000 * eps_f32
        float invn = valid ? (1.0f / norm) : 0.0f;
        for (int j = 0; j < ntx; j++) {
            float w = fmaxf(0.0f, 1.0f - fabsf(s - (float)(base + j)) * rks) * invn;
            s_wx2[ox * MAXTAPS + j] = make_float2(w, w);
        }
        // zero-pad one tap (pair loop rounds ntx up to even; ntx+1 <= 35 < 36)
        s_wx2[ox * MAXTAPS + ntx] = make_float2(0.f, 0.f);
        s_xb[ox] = base;
    } else if (tid < OUTW + OYT) {
        const int k  = tid - OUTW;
        const int oy = tile * OYT + k;
        float sy = ((float)oy + 0.5f) * inv_y - toff_y - 0.5f;
        int   yb = min(max((int)ceilf(sy - ks_y), 0), IN_H - nty);
        float norm = 0.0f;
        for (int j = 0; j < nty; j++)
            norm += fmaxf(0.0f, 1.0f - fabsf(sy - (float)(yb + j)) * rks_y);
        bool valid = (sy >= -0.5f) && (sy <= (float)IN_H - 0.5f)
                     && (fabsf(norm) > 1.1920929e-4f);
        s_sy[k]   = sy;
        s_invn[k] = valid ? (1.0f / norm) : 0.0f;
        s_yb[k]   = yb;
    }
    __syncthreads();

    // ---- phase 2: fill duplicated wy table over the row union ----
    const int rmin   = s_yb[0];                       // sy monotone in k
    const int rcount = s_yb[OYT - 1] + nty - rmin;    // <= 82
    for (int idx = tid; idx < rcount * OYT; idx += 256) {
        int r = idx >> 2, k = idx & (OYT - 1);
        float w = fmaxf(0.0f, 1.0f - fabsf(s_sy[k] - (float)(rmin + r)) * rks_y)
                  * s_invn[k];
        s_wyt2[idx] = make_float2(w, w);
    }
    __syncthreads();

    // active rows form one interval (y-windows of the 4 oy overlap)
    const int rlo = max(rmin, (int)ceilf(s_sy[0] - ks_y));
    const int rhi = min(rmin + rcount, (int)floorf(s_sy[OYT - 1] + ks_y) + 1);

    // ---- main loop: thread = (ox, c8); 4 oy x 8 ch accumulators ----
    const int ox = tid >> 3;        // 0..31
    const int c8 = tid & 7;         // 0..7
    const ulonglong2* __restrict__ wxp =
        (const ulonglong2*)&s_wx2[ox * MAXTAPS];   // 16B-aligned weight pairs
    const int np = (ntx + 1) >> 1;                 // tap pairs (zero-padded)

    // accumulators: a[k][p] = oy k, channel pair p (ch 2p, 2p+1)
    ull a0_0 = 0, a0_1 = 0, a0_2 = 0, a0_3 = 0;
    ull a1_0 = 0, a1_1 = 0, a1_2 = 0, a1_3 = 0;
    ull a2_0 = 0, a2_1 = 0, a2_2 = 0, a2_3 = 0;
    ull a3_0 = 0, a3_1 = 0, a3_2 = 0, a3_3 = 0;

    const uint4* __restrict__ rowp =
        g_fm16 + ((size_t)rlo * IN_W + s_xb[ox]) * NC8 + c8;
    const ulonglong2* __restrict__ wyp =
        (const ulonglong2*)&s_wyt2[(rlo - rmin) * OYT];

    for (int r = rlo; r < rhi; r++) {
        // x convolution: software-pipelined tap pairs — next pair's loads
        // issue before this pair's convert/FMA chain (MLP >= 4)
        ull r01 = 0, r23 = 0, r45 = 0, r67 = 0;
        const uint4* __restrict__ p = rowp;
        uint4 v0 = p[0];
        uint4 v1 = p[NC8];                     // may touch zero-weight pad tap
        for (int jp = 0; jp < np; jp++) {
            uint4 c0 = v0, c1 = v1;
            p += 2 * NC8;
            if (jp + 1 < np) {                 // prefetch next pair
                v0 = p[0];
                v1 = p[NC8];
            }
            ulonglong2 w01 = wxp[jp];          // LDS.128: 2 duplicated weights
            FMA2(r01, h2f(c0.x), w01.x);
            FMA2(r23, h2f(c0.y), w01.x);
            FMA2(r45, h2f(c0.z), w01.x);
            FMA2(r67, h2f(c0.w), w01.x);
            FMA2(r01, h2f(c1.x), w01.y);
            FMA2(r23, h2f(c1.y), w01.y);
            FMA2(r45, h2f(c1.z), w01.y);
            FMA2(r67, h2f(c1.w), w01.y);
        }

        // scatter into 4 oy accumulators; wy pairs via 2 x LDS.128
        ulonglong2 wy01 = wyp[0];
        ulonglong2 wy23 = wyp[1];
        FMA2(a0_0, r01, wy01.x);  FMA2(a0_1, r23, wy01.x);
        FMA2(a0_2, r45, wy01.x);  FMA2(a0_3, r67, wy01.x);
        FMA2(a1_0, r01, wy01.y);  FMA2(a1_1, r23, wy01.y);
        FMA2(a1_2, r45, wy01.y);  FMA2(a1_3, r67, wy01.y);
        FMA2(a2_0, r01, wy23.x);  FMA2(a2_1, r23, wy23.x);
        FMA2(a2_2, r45, wy23.x);  FMA2(a2_3, r67, wy23.x);
        FMA2(a3_0, r01, wy23.y);  FMA2(a3_1, r23, wy23.y);
        FMA2(a3_2, r45, wy23.y);  FMA2(a3_3, r67, wy23.y);

        rowp += IN_W * NC8;
        wyp  += 2;              // OYT pairs per row = 2 ulonglong2
    }

    // ---- write out[box][tile*4+k][ox][c8*8 .. +7] ----
    {
        float2* __restrict__ out2 = (float2*)out;
        size_t base =
            ((((size_t)box * OUTW + tile * OYT) * OUTW + ox) * NC8 + c8) * 4;
        const size_t st = (size_t)OUTW * NC8 * 4;   // one oy step in float2
        out2[base + 0] = *reinterpret_cast<float2*>(&a0_0);
        out2[base + 1] = *reinterpret_cast<float2*>(&a0_1);
        out2[base + 2] = *reinterpret_cast<float2*>(&a0_2);
        out2[base + 3] = *reinterpret_cast<float2*>(&a0_3);
        out2[base + st + 0] = *reinterpret_cast<float2*>(&a1_0);
        out2[base + st + 1] = *reinterpret_cast<float2*>(&a1_1);
        out2[base + st + 2] = *reinterpret_cast<float2*>(&a1_2);
        out2[base + st + 3] = *reinterpret_cast<float2*>(&a1_3);
        out2[base + 2*st + 0] = *reinterpret_cast<float2*>(&a2_0);
        out2[base + 2*st + 1] = *reinterpret_cast<float2*>(&a2_1);
        out2[base + 2*st + 2] = *reinterpret_cast<float2*>(&a2_2);
        out2[base + 2*st + 3] = *reinterpret_cast<float2*>(&a2_3);
        out2[base + 3*st + 0] = *reinterpret_cast<float2*>(&a3_0);
        out2[base + 3*st + 1] = *reinterpret_cast<float2*>(&a3_1);
        out2[base + 3*st + 2] = *reinterpret_cast<float2*>(&a3_2);
        out2[base + 3*st + 3] = *reinterpret_cast<float2*>(&a3_3);
    }
}

extern "C" void kernel_launch(void* const* d_in, const int* in_sizes, int n_in,
                              void* d_out, int out_size)
{
    const float* fm    = (const float*)d_in[0];   // [512, 512, 64] f32
    const float* boxes = (const float*)d_in[1];   // [512, 4] f32
    float* out = (float*)d_out;                   // [512, 32, 32, 64] f32

    // pre-pass: stage feature map as fp16 (2.1M c8-groups, 8 ch per thread)
    convert_kernel<<<(IN_H * IN_W * NC8) / 1024, 1024>>>(fm);

    dim3 grid(NTILES, NBOX);   // (oy-tile, box) -> 4096 CTAs
    roi_align_kernel<<<grid, 256>>>(boxes, out);
}

// round 16
// speedup vs baseline: 2.0126x; 1.4527x over previous
#include <cuda_runtime.h>
#include <cuda_fp16.h>

// feature_map [512,512,64] f32, boxes [512,4] f32 (cx,cy,w,h), out [512,32,32,64] f32
#define IN_H    512
#define IN_W    512
#define NC8     8           // channels as 8-channel groups (uint4 of 4 half2)
#define NBOX    512
#define OUTW    32
#define OYT     4           // oy rows per CTA tile
#define NTILES  (OUTW / OYT)
#define MAXTAPS 36          // ks < 16 -> taps <= 34; +pair pad
#define MAXROWS 88          // union of 4 oy windows: 3*inv + 2ks + 2 <= 82

typedef unsigned long long ull;

// fp16 staged copy of the feature map (32 MB device scratch; legal per rules).
// +64 px pad: pair-tap loop may read 1 px past the logical end at
// (row 511, rightmost window) with zero weight; pad is zero-init .bss.
__device__ uint4 g_fm16[(IN_H * IN_W + 64) * NC8];

// LPT schedule: boxes sorted by estimated work, descending.
__device__ int g_perm[NBOX];

// ---- pre-pass 1: f32 -> fp16 conversion, fully coalesced ----
__global__ __launch_bounds__(1024)
void convert_kernel(const float* __restrict__ fm)
{
    int i = blockIdx.x * 1024 + threadIdx.x;   // one c8 group per thread
    const float4 v0 = ((const float4*)fm)[2 * i];
    const float4 v1 = ((const float4*)fm)[2 * i + 1];
    __half2 a = __floats2half2_rn(v0.x, v0.y);
    __half2 b = __floats2half2_rn(v0.z, v0.w);
    __half2 c = __floats2half2_rn(v1.x, v1.y);
    __half2 d = __floats2half2_rn(v1.z, v1.w);
    uint4 o;
    o.x = *reinterpret_cast<unsigned*>(&a);
    o.y = *reinterpret_cast<unsigned*>(&b);
    o.z = *reinterpret_cast<unsigned*>(&c);
    o.w = *reinterpret_cast<unsigned*>(&d);
    g_fm16[i] = o;
}

// ---- pre-pass 2: rank boxes by work estimate (descending), bitonic sort ----
__global__ __launch_bounds__(NBOX)
void schedule_kernel(const float* __restrict__ boxes)
{
    __shared__ float sk[NBOX];
    __shared__ int   si[NBOX];
    const int tid = threadIdx.x;

    const float4 b = ((const float4*)boxes)[tid];
    float bw = fmaxf(b.z, 1e-6f);
    float bh = fmaxf(b.w, 1e-6f);
    float inv_x = (bw * 512.0f) / 32.0f;
    float ks_x  = fmaxf(inv_x, 1.0f);
    float inv_y = (bh * 512.0f) / 32.0f;
    float ks_y  = fmaxf(inv_y, 1.0f);
    float rows  = 3.0f * inv_y + 2.0f * ks_y + 2.0f;   // union rows (OYT=4)
    float pairs = ks_x + 2.0f;                          // ~ (ntx+1)/2
    sk[tid] = rows * pairs;
    si[tid] = tid;
    __syncthreads();

    // bitonic sort, descending by key (deterministic)
    for (int k = 2; k <= NBOX; k <<= 1) {
        for (int j = k >> 1; j > 0; j >>= 1) {
            int ixj = tid ^ j;
            if (ixj > tid) {
                bool desc = ((tid & k) == 0);
                float ka = sk[tid], kb = sk[ixj];
                bool swap = desc ? (ka < kb) : (ka > kb);
                if (swap) {
                    int ia = si[tid];
                    sk[tid] = kb;  sk[ixj] = ka;
                    si[tid] = si[ixj];  si[ixj] = ia;
                }
            }
            __syncthreads();
        }
    }
    g_perm[tid] = si[tid];
}

// half2 (packed in u32) -> f32x2 (packed in u64), lane order preserved
__device__ __forceinline__ ull h2f(unsigned h2)
{
    ull r;
    asm("{\n\t"
        ".reg .f16 a, b;\n\t"
        ".reg .f32 lo, hi;\n\t"
        "mov.b32 {a, b}, %1;\n\t"
        "cvt.f32.f16 lo, a;\n\t"
        "cvt.f32.f16 hi, b;\n\t"
        "mov.b64 %0, {lo, hi};\n\t"
        "}" : "=l"(r) : "r"(h2));
    return r;
}

// packed dual-FMA: acc.lane += v.lane * w.lane  (IEEE f32 per lane)
#define FMA2(acc, v, w) \
    asm("fma.rn.f32x2 %0, %1, %2, %0;" : "+l"(acc) : "l"(v), "l"(w))

// One CTA per (box, oy-tile of 4). 256 threads = 32 ox x 8 c8 lanes.
// Inner loop is the verified R12 champion, untouched. Boxes are processed
// in LPT order (g_perm) so straggler CTAs start first.
// Weight math replicates jax.image.scale_and_translate(method="linear",
// antialias=True) exactly (formulas verified since R4).
__global__ __launch_bounds__(256, 4)
void roi_align_kernel(const float* __restrict__ boxes,
                      float* __restrict__ out)
{
    __shared__ float2 s_wx2[OUTW * MAXTAPS];    // x weights, duplicated {w,w}
    __shared__ int    s_xb[OUTW];               // x window base per ox
    __shared__ float  s_sy[OYT];                // y sample pos per tile oy
    __shared__ float  s_invn[OYT];              // y norm (0 if invalid)
    __shared__ int    s_yb[OYT];                // y window base per tile oy
    __shared__ float2 s_wyt2[MAXROWS * OYT];    // y weights, duplicated {w,w}

    const int tile = blockIdx.x;             // 0..7
    const int box  = g_perm[blockIdx.y];     // LPT-ordered box id
    const int tid  = threadIdx.x;

    // ---- box parameters (all threads) ----
    const float4 b = ((const float4*)boxes)[box];
    float x0 = b.x - b.z * 0.5f;           // pre-clamp w/h (reference order)
    float y0 = b.y - b.w * 0.5f;
    float bw = fmaxf(b.z, 1e-6f);
    float bh = fmaxf(b.w, 1e-6f);

    float scale_x = 32.0f / (bw * 512.0f);
    float inv_x   = 1.0f / scale_x;
    float ks_x    = fmaxf(inv_x, 1.0f);
    float toff_x  = ((-x0 * 32.0f) / bw) * inv_x;
    int   ntx     = min((int)(2.0f * ks_x) + 2, 34);

    float scale_y = 32.0f / (bh * 512.0f);
    float inv_y   = 1.0f / scale_y;
    float ks_y    = fmaxf(inv_y, 1.0f);
    float toff_y  = ((-y0 * 32.0f) / bh) * inv_y;
    int   nty     = min((int)(2.0f * ks_y) + 2, 34);
    float rks_y   = 1.0f / ks_y;

    // ---- phase 1: per-ox x weights (threads 0..31), per-oy y params (32..35)
    if (tid < OUTW) {
        const int ox = tid;
        float s    = ((float)ox + 0.5f) * inv_x - toff_x - 0.5f;
        int   base = min(max((int)ceilf(s - ks_x), 0), IN_W - ntx);
        float rks  = 1.0f / ks_x;
        float norm = 0.0f;
        for (int j = 0; j < ntx; j++)
            norm += fmaxf(0.0f, 1.0f - fabsf(s - (float)(base + j)) * rks);
        bool valid = (s >= -0.5f) && (s <= (float)IN_W - 0.5f)
                     && (fabsf(norm) > 1.1920929e-4f);   // 1000 * eps_f32
        float invn = valid ? (1.0f / norm) : 0.0f;
        for (int j = 0; j < ntx; j++) {
            float w = fmaxf(0.0f, 1.0f - fabsf(s - (float)(base + j)) * rks) * invn;
            s_wx2[ox * MAXTAPS + j] = make_float2(w, w);
        }
        // zero-pad one tap (pair loop rounds ntx up to even; ntx+1 <= 35 < 36)
        s_wx2[ox * MAXTAPS + ntx] = make_float2(0.f, 0.f);
        s_xb[ox] = base;
    } else if (tid < OUTW + OYT) {
        const int k  = tid - OUTW;
        const int oy = tile * OYT + k;
        float sy = ((float)oy + 0.5f) * inv_y - toff_y - 0.5f;
        int   yb = min(max((int)ceilf(sy - ks_y), 0), IN_H - nty);
        float norm = 0.0f;
        for (int j = 0; j < nty; j++)
            norm += fmaxf(0.0f, 1.0f - fabsf(sy - (float)(yb + j)) * rks_y);
        bool valid = (sy >= -0.5f) && (sy <= (float)IN_H - 0.5f)
                     && (fabsf(norm) > 1.1920929e-4f);
        s_sy[k]   = sy;
        s_invn[k] = valid ? (1.0f / norm) : 0.0f;
        s_yb[k]   = yb;
    }
    __syncthreads();

    // ---- phase 2: fill duplicated wy table over the row union ----
    const int rmin   = s_yb[0];                       // sy monotone in k
    const int rcount = s_yb[OYT - 1] + nty - rmin;    // <= 82
    for (int idx = tid; idx < rcount * OYT; idx += 256) {
        int r = idx >> 2, k = idx & (OYT - 1);
        float w = fmaxf(0.0f, 1.0f - fabsf(s_sy[k] - (float)(rmin + r)) * rks_y)
                  * s_invn[k];
        s_wyt2[idx] = make_float2(w, w);
    }
    __syncthreads();

    // active rows form one interval (y-windows of the 4 oy overlap)
    const int rlo = max(rmin, (int)ceilf(s_sy[0] - ks_y));
    const int rhi = min(rmin + rcount, (int)floorf(s_sy[OYT - 1] + ks_y) + 1);

    // ---- main loop: thread = (ox, c8); 4 oy x 8 ch accumulators ----
    const int ox = tid >> 3;        // 0..31
    const int c8 = tid & 7;         // 0..7
    const ulonglong2* __restrict__ wxp =
        (const ulonglong2*)&s_wx2[ox * MAXTAPS];   // 16B-aligned weight pairs
    const int np = (ntx + 1) >> 1;                 // tap pairs (zero-padded)

    // accumulators: a[k][p] = oy k, channel pair p (ch 2p, 2p+1)
    ull a0_0 = 0, a0_1 = 0, a0_2 = 0, a0_3 = 0;
    ull a1_0 = 0, a1_1 = 0, a1_2 = 0, a1_3 = 0;
    ull a2_0 = 0, a2_1 = 0, a2_2 = 0, a2_3 = 0;
    ull a3_0 = 0, a3_1 = 0, a3_2 = 0, a3_3 = 0;

    const uint4* __restrict__ rowp =
        g_fm16 + ((size_t)rlo * IN_W + s_xb[ox]) * NC8 + c8;
    const ulonglong2* __restrict__ wyp =
        (const ulonglong2*)&s_wyt2[(rlo - rmin) * OYT];

    for (int r = rlo; r < rhi; r++) {
        // x convolution: pairs of taps, both LDG.128 issued before the FMAs
        ull r01 = 0, r23 = 0, r45 = 0, r67 = 0;
        const uint4* __restrict__ p = rowp;
        for (int jp = 0; jp < np; jp++) {
            uint4 v0 = p[0];
            uint4 v1 = p[NC8];                 // may touch zero-weight pad tap
            ulonglong2 w01 = wxp[jp];          // LDS.128: 2 duplicated weights
            FMA2(r01, h2f(v0.x), w01.x);
            FMA2(r23, h2f(v0.y), w01.x);
            FMA2(r45, h2f(v0.z), w01.x);
            FMA2(r67, h2f(v0.w), w01.x);
            FMA2(r01, h2f(v1.x), w01.y);
            FMA2(r23, h2f(v1.y), w01.y);
            FMA2(r45, h2f(v1.z), w01.y);
            FMA2(r67, h2f(v1.w), w01.y);
            p += 2 * NC8;
        }

        // scatter into 4 oy accumulators; wy pairs via 2 x LDS.128
        ulonglong2 wy01 = wyp[0];
        ulonglong2 wy23 = wyp[1];
        FMA2(a0_0, r01, wy01.x);  FMA2(a0_1, r23, wy01.x);
        FMA2(a0_2, r45, wy01.x);  FMA2(a0_3, r67, wy01.x);
        FMA2(a1_0, r01, wy01.y);  FMA2(a1_1, r23, wy01.y);
        FMA2(a1_2, r45, wy01.y);  FMA2(a1_3, r67, wy01.y);
        FMA2(a2_0, r01, wy23.x);  FMA2(a2_1, r23, wy23.x);
        FMA2(a2_2, r45, wy23.x);  FMA2(a2_3, r67, wy23.x);
        FMA2(a3_0, r01, wy23.y);  FMA2(a3_1, r23, wy23.y);
        FMA2(a3_2, r45, wy23.y);  FMA2(a3_3, r67, wy23.y);

        rowp += IN_W * NC8;
        wyp  += 2;              // OYT pairs per row = 2 ulonglong2
    }

    // ---- write out[box][tile*4+k][ox][c8*8 .. +7] ----
    {
        float2* __restrict__ out2 = (float2*)out;
        size_t base =
            ((((size_t)box * OUTW + tile * OYT) * OUTW + ox) * NC8 + c8) * 4;
        const size_t st = (size_t)OUTW * NC8 * 4;   // one oy step in float2
        out2[base + 0] = *reinterpret_cast<float2*>(&a0_0);
        out2[base + 1] = *reinterpret_cast<float2*>(&a0_1);
        out2[base + 2] = *reinterpret_cast<float2*>(&a0_2);
        out2[base + 3] = *reinterpret_cast<float2*>(&a0_3);
        out2[base + st + 0] = *reinterpret_cast<float2*>(&a1_0);
        out2[base + st + 1] = *reinterpret_cast<float2*>(&a1_1);
        out2[base + st + 2] = *reinterpret_cast<float2*>(&a1_2);
        out2[base + st + 3] = *reinterpret_cast<float2*>(&a1_3);
        out2[base + 2*st + 0] = *reinterpret_cast<float2*>(&a2_0);
        out2[base + 2*st + 1] = *reinterpret_cast<float2*>(&a2_1);
        out2[base + 2*st + 2] = *reinterpret_cast<float2*>(&a2_2);
        out2[base + 2*st + 3] = *reinterpret_cast<float2*>(&a2_3);
        out2[base + 3*st + 0] = *reinterpret_cast<float2*>(&a3_0);
        out2[base + 3*st + 1] = *reinterpret_cast<float2*>(&a3_1);
        out2[base + 3*st + 2] = *reinterpret_cast<float2*>(&a3_2);
        out2[base + 3*st + 3] = *reinterpret_cast<float2*>(&a3_3);
    }
}

extern "C" void kernel_launch(void* const* d_in, const int* in_sizes, int n_in,
                              void* d_out, int out_size)
{
    const float* fm    = (const float*)d_in[0];   // [512, 512, 64] f32
    const float* boxes = (const float*)d_in[1];   // [512, 4] f32
    float* out = (float*)d_out;                   // [512, 32, 32, 64] f32

    // pre-pass 1: stage feature map as fp16
    convert_kernel<<<(IN_H * IN_W * NC8) / 1024, 1024>>>(fm);
    // pre-pass 2: LPT schedule (sort boxes by estimated work, descending)
    schedule_kernel<<<1, NBOX>>>(boxes);

    dim3 grid(NTILES, NBOX);   // (oy-tile, perm slot) -> 4096 CTAs
    roi_align_kernel<<<grid, 256>>>(boxes, out);
}